// round 1
// baseline (speedup 1.0000x reference)
#include <cuda_runtime.h>
#include <math.h>

// Problem constants
#define N_TOK   131072      // 32 * 4096 tokens
#define DIM     64
#define KCODES  1024
#define TT      128         // tokens per block
#define CK      64          // codebook rows per chunk
#define NCHUNK  (KCODES / CK)   // 16
#define NB      (N_TOK / TT)    // 1024 blocks
#define NTHREADS 256

// Scratch (no device allocation allowed -> __device__ globals)
__device__ float g_wsq[KCODES];
__device__ int   g_counts[KCODES];
__device__ float g_part[NB];

// ---------------------------------------------------------------------------
// Kernel 0: wsq[k] = sum_j W[k][j]^2, zero counts
// ---------------------------------------------------------------------------
__global__ void vq_prep(const float* __restrict__ W) {
    int k = blockIdx.x * blockDim.x + threadIdx.x;
    if (k < KCODES) {
        const float* row = W + (size_t)k * DIM;
        float s = 0.f;
        #pragma unroll
        for (int j = 0; j < DIM; ++j) s += row[j] * row[j];
        g_wsq[k]    = s;
        g_counts[k] = 0;
    }
}

// ---------------------------------------------------------------------------
// Kernel 1: fused distance-GEMM + argmin + quantize + loss partial + counts
//   block = 256 threads (8 warps). Tokens on lanes (4/thread, contiguous),
//   codes on warps (8/warp per 64-row chunk).
//   smem: xs[64][128] transposed x tile (49152B total with union region).
// ---------------------------------------------------------------------------
__global__ void __launch_bounds__(NTHREADS)
vq_main(const float* __restrict__ x, const float* __restrict__ W,
        float* __restrict__ out)
{
    __shared__ float xs[DIM * TT];        // [j][t] transposed, 32KB
    __shared__ float region[CK * DIM];    // 16KB union: xsq / ws / (bd,bi,fidx)

    float* ws  = region;                          // [64][64] during chunks
    float* xsq = region;                          // [128] during prologue
    float* bd  = region;                          // [8][128] epilogue
    int*   bi  = (int*)(region + 8 * TT);         // [8][128]
    int*   fidx= (int*)(region + 16 * TT);        // [128]

    const int tid  = threadIdx.x;
    const int lane = tid & 31;
    const int wid  = tid >> 5;
    const int tbase = blockIdx.x * TT;
    const int t0 = lane * 4;                      // this thread's 4 tokens

    // ---- load x tile, transpose into smem ----
    for (int i = tid; i < TT * DIM / 4; i += NTHREADS) {
        int t  = i >> 4;               // 16 float4 per token
        int j4 = (i & 15) << 2;
        float4 v = *(const float4*)(x + (size_t)(tbase + t) * DIM + j4);
        xs[(j4 + 0) * TT + t] = v.x;
        xs[(j4 + 1) * TT + t] = v.y;
        xs[(j4 + 2) * TT + t] = v.z;
        xs[(j4 + 3) * TT + t] = v.w;
    }
    __syncthreads();

    // ---- xsq per token (mimic ||x||^2 term of reference distance) ----
    if (tid < TT) {
        float s = 0.f;
        for (int j = 0; j < DIM; ++j) { float v = xs[j * TT + tid]; s += v * v; }
        xsq[tid] = s;
    }
    __syncthreads();
    float xsqr[4];
    #pragma unroll
    for (int c = 0; c < 4; ++c) xsqr[c] = xsq[t0 + c];

    // ---- main loop over codebook chunks ----
    float bestd[4]; int besti[4];
    #pragma unroll
    for (int c = 0; c < 4; ++c) { bestd[c] = 3.0e38f; besti[c] = 0; }

    for (int ch = 0; ch < NCHUNK; ++ch) {
        __syncthreads();   // protects region reuse (xsq / previous ws)
        {
            const float4* src = (const float4*)(W + (size_t)ch * CK * DIM);
            float4* dst = (float4*)ws;
            for (int i = tid; i < CK * DIM / 4; i += NTHREADS) dst[i] = src[i];
        }
        __syncthreads();

        float acc[4][8];
        #pragma unroll
        for (int c = 0; c < 4; ++c)
            #pragma unroll
            for (int kk = 0; kk < 8; ++kk) acc[c][kk] = 0.f;

        const float* wbase = ws + wid * 8 * DIM;

        #pragma unroll 8
        for (int j4 = 0; j4 < DIM; j4 += 4) {
            // x for 4 tokens at 4 consecutive j (vector over tokens)
            float4 xq0 = *(const float4*)(xs + (j4 + 0) * TT + t0);
            float4 xq1 = *(const float4*)(xs + (j4 + 1) * TT + t0);
            float4 xq2 = *(const float4*)(xs + (j4 + 2) * TT + t0);
            float4 xq3 = *(const float4*)(xs + (j4 + 3) * TT + t0);
            #pragma unroll
            for (int kk = 0; kk < 8; ++kk) {
                float4 w4 = *(const float4*)(wbase + kk * DIM + j4);
                acc[0][kk] = fmaf(w4.x, xq0.x, acc[0][kk]);
                acc[0][kk] = fmaf(w4.y, xq1.x, acc[0][kk]);
                acc[0][kk] = fmaf(w4.z, xq2.x, acc[0][kk]);
                acc[0][kk] = fmaf(w4.w, xq3.x, acc[0][kk]);
                acc[1][kk] = fmaf(w4.x, xq0.y, acc[1][kk]);
                acc[1][kk] = fmaf(w4.y, xq1.y, acc[1][kk]);
                acc[1][kk] = fmaf(w4.z, xq2.y, acc[1][kk]);
                acc[1][kk] = fmaf(w4.w, xq3.y, acc[1][kk]);
                acc[2][kk] = fmaf(w4.x, xq0.z, acc[2][kk]);
                acc[2][kk] = fmaf(w4.y, xq1.z, acc[2][kk]);
                acc[2][kk] = fmaf(w4.z, xq2.z, acc[2][kk]);
                acc[2][kk] = fmaf(w4.w, xq3.z, acc[2][kk]);
                acc[3][kk] = fmaf(w4.x, xq0.w, acc[3][kk]);
                acc[3][kk] = fmaf(w4.y, xq1.w, acc[3][kk]);
                acc[3][kk] = fmaf(w4.z, xq2.w, acc[3][kk]);
                acc[3][kk] = fmaf(w4.w, xq3.w, acc[3][kk]);
            }
        }

        // distances + running argmin (ascending k -> lowest-index tie-break)
        int kg0 = ch * CK + wid * 8;
        #pragma unroll
        for (int kk = 0; kk < 8; ++kk) {
            float wsqv = g_wsq[kg0 + kk];
            #pragma unroll
            for (int c = 0; c < 4; ++c) {
                float a = wsqv + xsqr[c];          // fl(wsq + xsq) like reference
                float dist = fmaf(-2.f, acc[c][kk], a);
                if (dist < bestd[c]) { bestd[c] = dist; besti[c] = kg0 + kk; }
            }
        }
    }

    // ---- cross-warp argmin reduction ----
    __syncthreads();   // ws no longer needed; region becomes bd/bi/fidx
    #pragma unroll
    for (int c = 0; c < 4; ++c) {
        bd[wid * TT + t0 + c] = bestd[c];
        bi[wid * TT + t0 + c] = besti[c];
    }
    __syncthreads();
    if (tid < TT) {
        float bdv = bd[tid]; int biv = bi[tid];
        #pragma unroll
        for (int w = 1; w < 8; ++w) {
            float d2 = bd[w * TT + tid]; int i2 = bi[w * TT + tid];
            if (d2 < bdv || (d2 == bdv && i2 < biv)) { bdv = d2; biv = i2; }
        }
        fidx[tid] = biv;
        atomicAdd(&g_counts[biv], 1);   // integer atomics: deterministic
    }
    __syncthreads();

    // ---- epilogue: write quantized_st, accumulate loss partial ----
    float ls = 0.f;
    for (int s = tid; s < TT * 2; s += NTHREADS) {   // 32-float segments
        int t  = s >> 1;
        int j0 = (s & 1) * 32;
        int kb = fidx[t];
        const float* wrow = W + (size_t)kb * DIM + j0;
        float* orow = out + (size_t)(tbase + t) * DIM + j0;
        #pragma unroll
        for (int jj = 0; jj < 32; jj += 4) {
            float4 w4 = *(const float4*)(wrow + jj);
            float4 o;
            float xv, dq;
            // replicate reference: qst = x + (q - x), two fp32 roundings
            xv = xs[(j0 + jj + 0) * TT + t]; dq = w4.x - xv; o.x = xv + dq; ls = fmaf(dq, dq, ls);
            xv = xs[(j0 + jj + 1) * TT + t]; dq = w4.y - xv; o.y = xv + dq; ls = fmaf(dq, dq, ls);
            xv = xs[(j0 + jj + 2) * TT + t]; dq = w4.z - xv; o.z = xv + dq; ls = fmaf(dq, dq, ls);
            xv = xs[(j0 + jj + 3) * TT + t]; dq = w4.w - xv; o.w = xv + dq; ls = fmaf(dq, dq, ls);
            *(float4*)(orow + jj) = o;
        }
    }

    // deterministic fixed-order block reduce of loss into g_part
    __syncthreads();
    bd[tid] = ls;
    __syncthreads();
    for (int off = NTHREADS / 2; off > 0; off >>= 1) {
        if (tid < off) bd[tid] += bd[tid + off];
        __syncthreads();
    }
    if (tid == 0) g_part[blockIdx.x] = bd[0];
}

// ---------------------------------------------------------------------------
// Kernel 2: final scalars (loss, perplexity, usage)
// ---------------------------------------------------------------------------
__global__ void vq_final(float* __restrict__ out, int out_size) {
    __shared__ float red[1024];
    __shared__ float red2[1024];
    int tid = threadIdx.x;

    // sum of squared errors (fixed-order tree -> deterministic)
    red[tid] = g_part[tid];
    __syncthreads();
    for (int off = 512; off > 0; off >>= 1) {
        if (tid < off) red[tid] += red[tid + off];
        __syncthreads();
    }
    float sse = red[0];
    __syncthreads();

    // perplexity + usage from counts
    int c  = g_counts[tid];
    float p = (float)c / (float)N_TOK;
    red[tid]  = p * logf(p + 1e-10f);
    red2[tid] = (c >= 1) ? 1.f : 0.f;
    __syncthreads();
    for (int off = 512; off > 0; off >>= 1) {
        if (tid < off) { red[tid] += red[tid + off]; red2[tid] += red2[tid + off]; }
        __syncthreads();
    }
    if (tid == 0 && out_size >= N_TOK * DIM + 3) {
        float mse = sse / (float)(N_TOK * DIM);
        out[N_TOK * DIM + 0] = mse + 2.0f * mse;   // q_latent + 2*e_latent
        out[N_TOK * DIM + 1] = expf(-red[0]);
        out[N_TOK * DIM + 2] = red2[0];
    }
}

// ---------------------------------------------------------------------------
extern "C" void kernel_launch(void* const* d_in, const int* in_sizes, int n_in,
                              void* d_out, int out_size) {
    const float* x = (const float*)d_in[0];   // [32,4096,64] f32
    const float* W = (const float*)d_in[1];   // [1024,64] f32
    float* out = (float*)d_out;

    vq_prep<<<(KCODES + 255) / 256, 256>>>(W);
    vq_main<<<NB, NTHREADS>>>(x, W, out);
    vq_final<<<1, 1024>>>(out, out_size);
}